// round 1
// baseline (speedup 1.0000x reference)
#include <cuda_runtime.h>
#include <cstdint>
#include <cstddef>

// PndModelLSTM: 3-layer LSTM (H=64) over S=2048 steps, B=512, then FC(64->2).
// Strategy: batch rows are independent -> persistent per-CTA recurrence.
//   grid = 128 CTAs, each owns BT=4 batch rows for the whole sequence.
//   256 threads = 256 gate rows; thread g holds Whh[g][:] and Wih[g][:] in
//   registers packed as f32x2; per step it computes gates for its 4 batch rows
//   with fma.rn.f32x2 (2 MACs/instr), reading h/x from smem (warp-uniform
//   broadcast LDS.128, conflict-free). Gate activations done in-thread, cell
//   update done by the (b,j) = (tid>>6, tid&63) mapping with c-state in a
//   register. 2 barriers per step, no grid sync.
// Layers run as 3 sequential kernel launches; intermediate h sequences live in
// __device__ global buffers (allowed scratch; no allocation).

#define SQ   2048   // sequence length (after permute)
#define BB   512    // batch
#define HID  64
#define NG   256    // 4*H gates
#define BT   4      // batch rows per CTA

static __device__ float g_bufA[(size_t)SQ * BB * HID];  // 256 MB
static __device__ float g_bufB[(size_t)SQ * BB * HID];  // 256 MB

__device__ __forceinline__ unsigned long long fma2(unsigned long long a,
                                                   unsigned long long b,
                                                   unsigned long long c) {
    unsigned long long d;
    asm("fma.rn.f32x2 %0, %1, %2, %3;" : "=l"(d) : "l"(a), "l"(b), "l"(c));
    return d;
}

__device__ __forceinline__ float sigmoidf_(float x) {
    return 1.0f / (1.0f + __expf(-x));
}

template <bool L0, int SRCB, int DSTB, bool FINAL>
__global__ void __launch_bounds__(256, 1)
lstm_layer(const float* __restrict__ xin,   // only used when L0
           const float* __restrict__ Wih, const float* __restrict__ Whh,
           const float* __restrict__ bih, const float* __restrict__ bhh,
           const float* __restrict__ fcw, const float* __restrict__ fcb,
           float* __restrict__ out)
{
    __shared__ __align__(16) float hs[BT][HID];
    __shared__ __align__(16) float xsm[BT][HID];
    __shared__ float gsm[BT][NG];

    const int tid = threadIdx.x;
    const int b0  = blockIdx.x * BT;
    const float* src = L0 ? xin : (SRCB == 0 ? g_bufA : g_bufB);
    float* dst = (DSTB == 0 ? g_bufA : g_bufB);

    constexpr int IND = L0 ? 4 : HID;

    // ---- load this thread's weight rows into registers (packed f32x2) ----
    unsigned long long whh2[HID / 2];
    unsigned long long wih2[IND / 2];
#pragma unroll
    for (int k2 = 0; k2 < HID / 2; k2++)
        whh2[k2] = *(const unsigned long long*)(Whh + (size_t)tid * HID + 2 * k2);
#pragma unroll
    for (int k2 = 0; k2 < IND / 2; k2++)
        wih2[k2] = *(const unsigned long long*)(Wih + (size_t)tid * IND + 2 * k2);
    const float bias = bih[tid] + bhh[tid];
    const int gtype = tid >> 6;           // 0:i 1:f 2:g 3:o

    const int ub = tid >> 6, uj = tid & 63;   // this thread's (batch,hidden) for update
    float c_state = 0.0f;
    hs[ub][uj] = 0.0f;

    // ---- prefetch x for t=0 ----
    float xf = 0.0f;
    if (L0) {
        if (tid < BT * 4)
            xf = xin[(size_t)(b0 + (tid >> 2)) * (SQ * 4) + (tid & 3)];
    } else {
        xf = src[((size_t)0 * BB + b0 + ub) * HID + uj];
    }
    __syncthreads();

    for (int t = 0; t < SQ; t++) {
        // commit prefetched x_t to smem
        if (L0) {
            if (tid < BT * 4) xsm[tid >> 2][tid & 3] = xf;
        } else {
            xsm[ub][uj] = xf;
        }
        __syncthreads();   // xsm + hs(from prev update) visible

        // prefetch x_{t+1} (long-latency load overlapped with the FMA loop)
        if (t + 1 < SQ) {
            if (L0) {
                if (tid < BT * 4)
                    xf = xin[(size_t)(b0 + (tid >> 2)) * (SQ * 4) + (size_t)(t + 1) * 4 + (tid & 3)];
            } else {
                xf = src[((size_t)(t + 1) * BB + b0 + ub) * HID + uj];
            }
        }

        // ---- gate GEMM: acc[b] (f32x2) += W row . [h | x] ----
        unsigned long long acc[BT];
#pragma unroll
        for (int b = 0; b < BT; b++) acc[b] = 0ULL;   // (0.f,0.f)

#pragma unroll
        for (int k4 = 0; k4 < HID / 4; k4++) {
            unsigned long long w0 = whh2[2 * k4], w1 = whh2[2 * k4 + 1];
#pragma unroll
            for (int b = 0; b < BT; b++) {
                ulonglong2 hv = *(const ulonglong2*)(&hs[b][4 * k4]);
                acc[b] = fma2(w0, hv.x, acc[b]);
                acc[b] = fma2(w1, hv.y, acc[b]);
            }
        }
        if (L0) {
#pragma unroll
            for (int b = 0; b < BT; b++) {
                ulonglong2 xv = *(const ulonglong2*)(&xsm[b][0]);
                acc[b] = fma2(wih2[0], xv.x, acc[b]);
                acc[b] = fma2(wih2[1], xv.y, acc[b]);
            }
        } else {
#pragma unroll
            for (int k4 = 0; k4 < HID / 4; k4++) {
                unsigned long long w0 = wih2[2 * k4], w1 = wih2[2 * k4 + 1];
#pragma unroll
                for (int b = 0; b < BT; b++) {
                    ulonglong2 xv = *(const ulonglong2*)(&xsm[b][4 * k4]);
                    acc[b] = fma2(w0, xv.x, acc[b]);
                    acc[b] = fma2(w1, xv.y, acc[b]);
                }
            }
        }

        // ---- activations, store gates to smem ----
#pragma unroll
        for (int b = 0; b < BT; b++) {
            union { unsigned long long u; float2 f; } cv; cv.u = acc[b];
            float v = cv.f.x + cv.f.y + bias;
            gsm[b][tid] = (gtype == 2) ? tanhf(v) : sigmoidf_(v);
        }
        __syncthreads();   // all gates visible

        // ---- cell/hidden update: thread -> (ub, uj) ----
        {
            float iv = gsm[ub][uj];
            float fv = gsm[ub][HID + uj];
            float gv = gsm[ub][2 * HID + uj];
            float ov = gsm[ub][3 * HID + uj];
            c_state = fv * c_state + iv * gv;
            float h = ov * tanhf(c_state);
            hs[ub][uj] = h;
            if (!FINAL)
                dst[((size_t)t * BB + b0 + ub) * HID + uj] = h;
        }
        // hs writes are ordered before next step's reads by the barrier at the
        // top of the next iteration (xsm commit -> __syncthreads).
    }

    if (FINAL) {
        __syncthreads();   // final hs visible to all
        if (tid < BT * 2) {
            int b = tid >> 1, o = tid & 1;
            float s = fcb[o];
#pragma unroll
            for (int j = 0; j < HID; j++)
                s += hs[b][j] * fcw[o * HID + j];
            out[(b0 + b) * 2 + o] = s;
        }
    }
}

extern "C" void kernel_launch(void* const* d_in, const int* in_sizes, int n_in,
                              void* d_out, int out_size)
{
    (void)in_sizes; (void)n_in; (void)out_size;
    const float* x    = (const float*)d_in[0];
    const float* Wih0 = (const float*)d_in[1];
    const float* Whh0 = (const float*)d_in[2];
    const float* bih0 = (const float*)d_in[3];
    const float* bhh0 = (const float*)d_in[4];
    const float* Wih1 = (const float*)d_in[5];
    const float* Whh1 = (const float*)d_in[6];
    const float* bih1 = (const float*)d_in[7];
    const float* bhh1 = (const float*)d_in[8];
    const float* Wih2 = (const float*)d_in[9];
    const float* Whh2 = (const float*)d_in[10];
    const float* bih2 = (const float*)d_in[11];
    const float* bhh2 = (const float*)d_in[12];
    const float* fc_w = (const float*)d_in[13];
    const float* fc_b = (const float*)d_in[14];
    float* out = (float*)d_out;

    dim3 grid(BB / BT), block(256);
    // layer 0: x -> g_bufA
    lstm_layer<true, 0, 0, false><<<grid, block>>>(x, Wih0, Whh0, bih0, bhh0,
                                                   nullptr, nullptr, nullptr);
    // layer 1: g_bufA -> g_bufB
    lstm_layer<false, 0, 1, false><<<grid, block>>>(nullptr, Wih1, Whh1, bih1, bhh1,
                                                    nullptr, nullptr, nullptr);
    // layer 2: g_bufB -> (final h only) -> FC -> out
    lstm_layer<false, 1, 0, true><<<grid, block>>>(nullptr, Wih2, Whh2, bih2, bhh2,
                                                   fc_w, fc_b, out);
}

// round 2
// speedup vs baseline: 1.0635x; 1.0635x over previous
#include <cuda_runtime.h>
#include <cstdint>
#include <cstddef>

// 3-layer LSTM (H=64), S=2048, B=512, FC(64->2).
// Persistent per-CTA recurrence, weights register-stationary, K-split pairs.
//   grid=128 CTAs (BT=4 batch rows each), block=512 threads.
//   Thread (g = tid>>1, kh = tid&1): gate row g, K-half kh.
//   Each thread holds 32 Whh floats + 32 Wih floats (f32x2 packed) -> ~95 regs
//   -> 16 warps/SM (vs 8 before) for latency hiding.
//   Partial gate sums combined with shfl.bfly(1); activations via
//   ex2.approx/rcp.approx; h/x halves padded to 144B stride so the two
//   kh broadcast groups hit disjoint smem banks.

#define SQ   2048
#define BB   512
#define HID  64
#define NG   256
#define BT   4
#define HSTR 36     // padded half-stride in floats (32 data + 4 pad)

static __device__ float g_bufA[(size_t)SQ * BB * HID];
static __device__ float g_bufB[(size_t)SQ * BB * HID];

__device__ __forceinline__ unsigned long long fma2(unsigned long long a,
                                                   unsigned long long b,
                                                   unsigned long long c) {
    unsigned long long d;
    asm("fma.rn.f32x2 %0, %1, %2, %3;" : "=l"(d) : "l"(a), "l"(b), "l"(c));
    return d;
}
__device__ __forceinline__ float ex2a(float x) {
    float y; asm("ex2.approx.f32 %0, %1;" : "=f"(y) : "f"(x)); return y;
}
__device__ __forceinline__ float rcpa(float x) {
    float y; asm("rcp.approx.f32 %0, %1;" : "=f"(y) : "f"(x)); return y;
}
__device__ __forceinline__ float sigf(float x) {
    return rcpa(1.0f + ex2a(-1.4426950408889634f * x));
}
__device__ __forceinline__ float tanh_(float x) {
    return 2.0f * rcpa(1.0f + ex2a(-2.8853900817779268f * x)) - 1.0f;
}

template <bool L0, int SRCB, int DSTB, bool FINAL>
__global__ void __launch_bounds__(512, 1)
lstm_layer(const float* __restrict__ xin,
           const float* __restrict__ Wih, const float* __restrict__ Whh,
           const float* __restrict__ bih, const float* __restrict__ bhh,
           const float* __restrict__ fcw, const float* __restrict__ fcb,
           float* __restrict__ out)
{
    // [b][kh][c]: halves 144B apart -> bank groups disjoint (36 mod 32 = 4)
    __shared__ __align__(16) float hs [BT][2][HSTR];
    __shared__ __align__(16) float xsm[BT][2][HSTR];
    __shared__ float gsm[BT][NG];

    const int tid = threadIdx.x;
    const int g   = tid >> 1;      // gate row 0..255
    const int kh  = tid & 1;       // K-half
    const int b0  = blockIdx.x * BT;
    const float* src = L0 ? xin : (SRCB == 0 ? g_bufA : g_bufB);
    float* dst = (DSTB == 0 ? g_bufA : g_bufB);

    // ---- weights for this (g, kh): 32 Whh cols (+32 Wih cols / 4 x cols) ----
    unsigned long long whh2[16];
    unsigned long long wih2[16];
#pragma unroll
    for (int k2 = 0; k2 < 16; k2++)
        whh2[k2] = *(const unsigned long long*)(Whh + (size_t)g * HID + kh * 32 + 2 * k2);
    if (L0) {
        if (kh == 0) {
            wih2[0] = *(const unsigned long long*)(Wih + (size_t)g * 4);
            wih2[1] = *(const unsigned long long*)(Wih + (size_t)g * 4 + 2);
        }
    } else {
#pragma unroll
        for (int k2 = 0; k2 < 16; k2++)
            wih2[k2] = *(const unsigned long long*)(Wih + (size_t)g * HID + kh * 32 + 2 * k2);
    }
    const float bias  = bih[g] + bhh[g];
    const int   gtype = g >> 6;                 // 0:i 1:f 2:g 3:o

    // update-thread mapping (even threads, kh==0): u = g -> (ub, uj)
    const int ub = g >> 6, uj = g & 63;
    float c_state = 0.0f;

    // init h = 0 (even threads own the 256 h slots)
    if (kh == 0) hs[ub][uj >> 5][uj & 31] = 0.0f;

    // ---- prefetch x for t=0 ----
    float xf = 0.0f;
    if (L0) {
        if (kh == 0 && g < BT * 4)
            xf = xin[(size_t)(b0 + (g >> 2)) * (SQ * 4) + (g & 3)];
    } else {
        if (kh == 0)
            xf = src[((size_t)0 * BB + b0 + ub) * HID + uj];
    }
    __syncthreads();

    for (int t = 0; t < SQ; t++) {
        // commit prefetched x_t
        if (L0) {
            if (kh == 0 && g < BT * 4) xsm[g >> 2][0][g & 3] = xf;
        } else {
            if (kh == 0) xsm[ub][uj >> 5][uj & 31] = xf;
        }
        __syncthreads();   // (A) xsm + hs(prev update) visible

        // prefetch x_{t+1} early: ~full step of FMA to cover the latency
        if (t + 1 < SQ) {
            if (L0) {
                if (kh == 0 && g < BT * 4)
                    xf = xin[(size_t)(b0 + (g >> 2)) * (SQ * 4) + (size_t)(t + 1) * 4 + (g & 3)];
            } else {
                if (kh == 0)
                    xf = src[((size_t)(t + 1) * BB + b0 + ub) * HID + uj];
            }
        }

        // ---- half-gate GEMM ----
        unsigned long long acc[BT];
#pragma unroll
        for (int b = 0; b < BT; b++) acc[b] = 0ULL;

#pragma unroll
        for (int k4 = 0; k4 < 8; k4++) {
            unsigned long long w0 = whh2[2 * k4], w1 = whh2[2 * k4 + 1];
#pragma unroll
            for (int b = 0; b < BT; b++) {
                ulonglong2 hv = *(const ulonglong2*)(&hs[b][kh][4 * k4]);
                acc[b] = fma2(w0, hv.x, acc[b]);
                acc[b] = fma2(w1, hv.y, acc[b]);
            }
        }
        if (L0) {
            if (kh == 0) {
#pragma unroll
                for (int b = 0; b < BT; b++) {
                    ulonglong2 xv = *(const ulonglong2*)(&xsm[b][0][0]);
                    acc[b] = fma2(wih2[0], xv.x, acc[b]);
                    acc[b] = fma2(wih2[1], xv.y, acc[b]);
                }
            }
        } else {
#pragma unroll
            for (int k4 = 0; k4 < 8; k4++) {
                unsigned long long w0 = wih2[2 * k4], w1 = wih2[2 * k4 + 1];
#pragma unroll
                for (int b = 0; b < BT; b++) {
                    ulonglong2 xv = *(const ulonglong2*)(&xsm[b][kh][4 * k4]);
                    acc[b] = fma2(w0, xv.x, acc[b]);
                    acc[b] = fma2(w1, xv.y, acc[b]);
                }
            }
        }

        // ---- pair reduction + activations (parity-split over b) ----
        float s[BT];
#pragma unroll
        for (int b = 0; b < BT; b++) {
            union { unsigned long long u; float2 f; } cv; cv.u = acc[b];
            s[b] = cv.f.x + cv.f.y;
        }
#pragma unroll
        for (int b = 0; b < BT; b++)
            s[b] += __shfl_xor_sync(0xffffffffu, s[b], 1);

#pragma unroll
        for (int bb = 0; bb < 2; bb++) {
            int b = 2 * kh + bb;
            float v = s[b] + bias;
            gsm[b][g] = (gtype == 2) ? tanh_(v) : sigf(v);
        }
        __syncthreads();   // (B) gates visible

        // ---- cell/hidden update on even threads ----
        if (kh == 0) {
            float iv = gsm[ub][uj];
            float fv = gsm[ub][HID + uj];
            float gv = gsm[ub][2 * HID + uj];
            float ov = gsm[ub][3 * HID + uj];
            c_state = fv * c_state + iv * gv;
            float h = ov * tanh_(c_state);
            hs[ub][uj >> 5][uj & 31] = h;
            if (!FINAL)
                dst[((size_t)t * BB + b0 + ub) * HID + uj] = h;
        }
        // hs writes ordered before next step's reads by barrier (A)
    }

    if (FINAL) {
        __syncthreads();
        if (tid < BT * 2) {
            int b = tid >> 1, o = tid & 1;
            float sum = fcb[o];
#pragma unroll
            for (int j = 0; j < HID; j++)
                sum += hs[b][j >> 5][j & 31] * fcw[o * HID + j];
            out[(b0 + b) * 2 + o] = sum;
        }
    }
}

extern "C" void kernel_launch(void* const* d_in, const int* in_sizes, int n_in,
                              void* d_out, int out_size)
{
    (void)in_sizes; (void)n_in; (void)out_size;
    const float* x    = (const float*)d_in[0];
    const float* Wih0 = (const float*)d_in[1];
    const float* Whh0 = (const float*)d_in[2];
    const float* bih0 = (const float*)d_in[3];
    const float* bhh0 = (const float*)d_in[4];
    const float* Wih1 = (const float*)d_in[5];
    const float* Whh1 = (const float*)d_in[6];
    const float* bih1 = (const float*)d_in[7];
    const float* bhh1 = (const float*)d_in[8];
    const float* Wih2 = (const float*)d_in[9];
    const float* Whh2 = (const float*)d_in[10];
    const float* bih2 = (const float*)d_in[11];
    const float* bhh2 = (const float*)d_in[12];
    const float* fc_w = (const float*)d_in[13];
    const float* fc_b = (const float*)d_in[14];
    float* out = (float*)d_out;

    dim3 grid(BB / BT), block(512);
    lstm_layer<true, 0, 0, false><<<grid, block>>>(x, Wih0, Whh0, bih0, bhh0,
                                                   nullptr, nullptr, nullptr);
    lstm_layer<false, 0, 1, false><<<grid, block>>>(nullptr, Wih1, Whh1, bih1, bhh1,
                                                    nullptr, nullptr, nullptr);
    lstm_layer<false, 1, 0, true><<<grid, block>>>(nullptr, Wih2, Whh2, bih2, bhh2,
                                                   fc_w, fc_b, out);
}